// round 4
// baseline (speedup 1.0000x reference)
#include <cuda_runtime.h>
#include <math.h>

typedef unsigned long long ull;

#define BB 64
#define TT 512
#define II 256
#define HH 512
#define CC 40
#define G4 2048     // 4*H
#define NB 128      // persistent blocks, all co-resident (<=148 SMs, 1 block/SM)

// -------------------- device scratch --------------------
__device__ __align__(256) float g_xg [(size_t)BB * TT * G4];   // [m=b*T+t][n]
__device__ __align__(256) float g_xgT[(size_t)TT * G4 * BB];   // [t][n][b]
__device__ __align__(256) float g_hbuf[2 * HH * BB];           // [parity][unit][b]
__device__ volatile unsigned g_flags[NB * 32];                 // one 128B line per block
__device__ volatile unsigned g_gen2;                           // generation word

// -------------------- f32x2 helpers --------------------
__device__ __forceinline__ ull pack2(float x, float y) {
    ull r; asm("mov.b64 %0, {%1, %2};" : "=l"(r) : "f"(x), "f"(y)); return r;
}
__device__ __forceinline__ void unpack2(ull v, float& x, float& y) {
    asm("mov.b64 {%0, %1}, %2;" : "=f"(x), "=f"(y) : "l"(v));
}
__device__ __forceinline__ ull ffma2(ull a, ull b, ull c) {
    ull d; asm("fma.rn.f32x2 %0, %1, %2, %3;" : "=l"(d) : "l"(a), "l"(b), "l"(c)); return d;
}

// fast activations (MUFU-based; err ~1e-6, well within 1e-3 budget)
__device__ __forceinline__ float fsig(float x) {
    return __fdividef(1.f, 1.f + __expf(-x));
}
__device__ __forceinline__ float ftanh(float x) {
    float ax = fabsf(x);
    float e  = __expf(-2.f * ax);
    float r  = __fdividef(1.f - e, 1.f + e);
    return x < 0.f ? -r : r;
}

// -------------------- flag-tree grid barrier --------------------
// Every block writes its own flag line; block 0 polls all flags in parallel
// (128 threads, one flag each), then publishes g_gen2 = e. Monotone epochs,
// base read at kernel entry -> safe across graph replays without resets.
// __nanosleep backoff keeps 128 spinning SMs from hammering the L2 line.
__device__ __forceinline__ void gridbar(int bx, int tid, unsigned e) {
    __threadfence();
    __syncthreads();
    if (bx == 0) {
        if (tid > 0 && tid < NB) {
            while ((int)(g_flags[tid * 32] - e) < 0) { __nanosleep(32); }
        }
        __syncthreads();
        if (tid == 0) { __threadfence(); g_gen2 = e; }
    } else {
        if (tid == 0) {
            g_flags[bx * 32] = e;
            while ((int)(g_gen2 - e) < 0) { __nanosleep(32); }
            __threadfence();
        }
        __syncthreads();
    }
}

// -------------------- kernel 1: xg = x @ W_ih^T + (b_ih + b_hh), f32x2 --------------------
__global__ void __launch_bounds__(256) gemm_xg(const float* __restrict__ x,
                                               const float* __restrict__ Wih,
                                               const float* __restrict__ bih,
                                               const float* __restrict__ bhh) {
    __shared__ __align__(16) float As[16][132];   // [k][m]
    __shared__ __align__(16) float Bs[16][132];   // [k][n]
    const int tid  = threadIdx.x;
    const int m0   = blockIdx.y * 128;
    const int n0   = blockIdx.x * 128;
    const int tx   = tid & 15;
    const int ty   = tid >> 4;
    const int lrow = tid >> 2;
    const int lkq  = (tid & 3) << 2;

    ull acc2[8][4];
#pragma unroll
    for (int i = 0; i < 8; i++)
#pragma unroll
        for (int j = 0; j < 4; j++) acc2[i][j] = 0ull;

    for (int k0 = 0; k0 < II; k0 += 16) {
        float4 a0 = *(const float4*)(x   + (size_t)(m0 + lrow)      * II + k0 + lkq);
        float4 a1 = *(const float4*)(x   + (size_t)(m0 + lrow + 64) * II + k0 + lkq);
        float4 b0 = *(const float4*)(Wih + (size_t)(n0 + lrow)      * II + k0 + lkq);
        float4 b1 = *(const float4*)(Wih + (size_t)(n0 + lrow + 64) * II + k0 + lkq);
        __syncthreads();
        As[lkq+0][lrow]    = a0.x; As[lkq+1][lrow]    = a0.y;
        As[lkq+2][lrow]    = a0.z; As[lkq+3][lrow]    = a0.w;
        As[lkq+0][lrow+64] = a1.x; As[lkq+1][lrow+64] = a1.y;
        As[lkq+2][lrow+64] = a1.z; As[lkq+3][lrow+64] = a1.w;
        Bs[lkq+0][lrow]    = b0.x; Bs[lkq+1][lrow]    = b0.y;
        Bs[lkq+2][lrow]    = b0.z; Bs[lkq+3][lrow]    = b0.w;
        Bs[lkq+0][lrow+64] = b1.x; Bs[lkq+1][lrow+64] = b1.y;
        Bs[lkq+2][lrow+64] = b1.z; Bs[lkq+3][lrow+64] = b1.w;
        __syncthreads();
#pragma unroll
        for (int k = 0; k < 16; k++) {
            float a[8];
            *(float4*)(a)     = *(float4*)&As[k][ty * 8];
            *(float4*)(a + 4) = *(float4*)&As[k][ty * 8 + 4];
            ulonglong2 bA = *(ulonglong2*)&Bs[k][tx * 8];
            ulonglong2 bB = *(ulonglong2*)&Bs[k][tx * 8 + 4];
            ull b2[4] = {bA.x, bA.y, bB.x, bB.y};
#pragma unroll
            for (int i = 0; i < 8; i++) {
                ull a2 = pack2(a[i], a[i]);
                acc2[i][0] = ffma2(a2, b2[0], acc2[i][0]);
                acc2[i][1] = ffma2(a2, b2[1], acc2[i][1]);
                acc2[i][2] = ffma2(a2, b2[2], acc2[i][2]);
                acc2[i][3] = ffma2(a2, b2[3], acc2[i][3]);
            }
        }
    }

    float bias[8];
#pragma unroll
    for (int j = 0; j < 8; j++) {
        int n = n0 + tx * 8 + j;
        bias[j] = bih[n] + bhh[n];
    }
#pragma unroll
    for (int i = 0; i < 8; i++) {
        size_t m = (size_t)(m0 + ty * 8 + i);
        float o[8];
#pragma unroll
        for (int j = 0; j < 4; j++) unpack2(acc2[i][j], o[2*j], o[2*j+1]);
        float4 v0, v1;
        v0.x = o[0] + bias[0]; v0.y = o[1] + bias[1];
        v0.z = o[2] + bias[2]; v0.w = o[3] + bias[3];
        v1.x = o[4] + bias[4]; v1.y = o[5] + bias[5];
        v1.z = o[6] + bias[6]; v1.w = o[7] + bias[7];
        *(float4*)(g_xg + m * G4 + n0 + tx * 8)     = v0;
        *(float4*)(g_xg + m * G4 + n0 + tx * 8 + 4) = v1;
    }
}

// -------------------- kernel 2: transpose xg[b*T+t][n] -> xgT[t][n][b] --------------------
__global__ void __launch_bounds__(256) transpose_xg() {
    __shared__ float tile[64][65];
    const int t   = blockIdx.x;
    const int n0  = blockIdx.y << 6;
    const int tid = threadIdx.x;
    const int a   = tid & 63;
    const int r   = tid >> 6;
    for (int b = r; b < 64; b += 4)
        tile[a][b] = g_xg[(size_t)(b * TT + t) * G4 + n0 + a];
    __syncthreads();
    for (int n = r; n < 64; n += 4)
        g_xgT[((size_t)t * G4 + n0 + n) * BB + a] = tile[n][a];
}

// -------------------- kernel 3: persistent LSTM recurrence (f32x2) --------------------
// smem: hsT (h k-major, 128KB) | Wsm2 (16 x 512 dup-pairs, 64KB) | red (16KB)
#define SMEM_LSTM (HH * 64 * 4 + 16 * 512 * 8 + 4 * 16 * 64 * 4)
__global__ void __launch_bounds__(256, 1) lstm_rec(const float* __restrict__ Whh) {
    extern __shared__ char smc[];
    ull*   hsT2 = (ull*)smc;                            // [512][32]  h[k][b-pairs]
    ull*   Wsm2 = (ull*)(smc + HH * 64 * 4);            // [16][512]  {w,w}
    float* red  = (float*)(smc + HH * 64 * 4 + 16 * 512 * 8);  // [4][16][64]
    ull*   red2 = (ull*)red;

    const int tid = threadIdx.x;
    const int bx  = blockIdx.x;
    unsigned base = g_gen2;   // persistent epoch base (volatile read)

    // Load W_hh slice, duplicated into both f32x2 halves
    for (int idx = tid; idx < 16 * 512; idx += 256) {
        int lr  = idx >> 9;
        int k   = idx & 511;
        int row = ((lr >> 2) << 9) + (bx << 2) + (lr & 3);
        float w = Whh[(size_t)row * HH + k];
        Wsm2[(lr << 9) + k] = pack2(w, w);
    }

    // elementwise-role mapping
    const int b  = tid & 63;
    const int uu = tid >> 6;
    const int ug = (bx << 2) + uu;

    g_hbuf[ug * 64 + b] = 0.f;    // h0 = 0 (parity 0)
    float c = 0.f;
    unsigned e = base + 1;
    gridbar(bx, tid, e); e++;

    // compute-role mapping: split-k x4, 2 rows x 8 batches (4 f32x2) per thread
    const int kg = tid >> 6;
    const int rq = (tid >> 3) & 7;
    const int bq = tid & 7;
    const int k0 = kg << 7;
    const ull* w0p = Wsm2 + ((rq * 2) << 9);
    const ull* w1p = w0p + 512;
    const int  rb  = ((kg << 4) + (rq << 1)) * 32 + (bq << 2);
    const unsigned sbase = (unsigned)__cvta_generic_to_shared(smc) + tid * 16;

    for (int t = 0; t < TT; t++) {
        const int p = t & 1;

        // prefetch xg for this step (independent of h -> DRAM latency hidden)
        float xgv[4];
#pragma unroll
        for (int g = 0; g < 4; g++)
            xgv[g] = __ldg(&g_xgT[((size_t)t * G4 + (g << 9) + ug) * 64 + b]);

        // stage h into smem via cp.async.cg (L2-fresh, bypass L1)
        {
            const char* g0 = (const char*)(g_hbuf + p * HH * 64) + tid * 16;
#pragma unroll
            for (int i = 0; i < 32; i++)
                asm volatile("cp.async.cg.shared.global [%0], [%1], 16;"
                             :: "r"(sbase + i * 4096), "l"(g0 + i * 4096));
            asm volatile("cp.async.commit_group;");
            asm volatile("cp.async.wait_group 0;");
        }
        __syncthreads();

        ull acc0[4], acc1[4];
#pragma unroll
        for (int j = 0; j < 4; j++) { acc0[j] = 0ull; acc1[j] = 0ull; }

#pragma unroll 8
        for (int k = k0; k < k0 + 128; k++) {
            ulonglong2 ha = *(const ulonglong2*)(hsT2 + (k << 5) + (bq << 2));
            ulonglong2 hb = *(const ulonglong2*)(hsT2 + (k << 5) + (bq << 2) + 2);
            ull w0 = w0p[k];
            ull w1 = w1p[k];
            acc0[0] = ffma2(w0, ha.x, acc0[0]);
            acc0[1] = ffma2(w0, ha.y, acc0[1]);
            acc0[2] = ffma2(w0, hb.x, acc0[2]);
            acc0[3] = ffma2(w0, hb.y, acc0[3]);
            acc1[0] = ffma2(w1, ha.x, acc1[0]);
            acc1[1] = ffma2(w1, ha.y, acc1[1]);
            acc1[2] = ffma2(w1, hb.x, acc1[2]);
            acc1[3] = ffma2(w1, hb.y, acc1[3]);
        }

        *(ulonglong2*)(red2 + rb)      = make_ulonglong2(acc0[0], acc0[1]);
        *(ulonglong2*)(red2 + rb + 2)  = make_ulonglong2(acc0[2], acc0[3]);
        *(ulonglong2*)(red2 + rb + 32) = make_ulonglong2(acc1[0], acc1[1]);
        *(ulonglong2*)(red2 + rb + 34) = make_ulonglong2(acc1[2], acc1[3]);
        __syncthreads();

        // elementwise: combine split-k partials + xg, gates, state update
        float s[4];
#pragma unroll
        for (int g = 0; g < 4; g++) {
            int lr = (g << 2) + uu;
            float v = red[lr * 64 + b] + red[(16 + lr) * 64 + b]
                    + red[(32 + lr) * 64 + b] + red[(48 + lr) * 64 + b];
            s[g] = v + xgv[g];
        }
        float ig = fsig(s[0]);
        float fg = fsig(s[1]);
        float gg = ftanh(s[2]);
        float og = fsig(s[3]);
        c = fmaf(fg, c, ig * gg);
        float h = og * ftanh(c);
        g_hbuf[((p ^ 1) * HH + ug) * 64 + b] = h;
        gridbar(bx, tid, e); e++;
    }
    // h_last in parity 0
}

// -------------------- kernel 4: out = h_last @ W_fc^T + b_fc --------------------
__global__ void __launch_bounds__(256) fc_out(const float* __restrict__ Wfc,
                                              const float* __restrict__ bfc,
                                              float* __restrict__ out) {
    __shared__ float hs[HH];
    const int b = blockIdx.x;
    for (int u = threadIdx.x; u < HH; u += 256) hs[u] = g_hbuf[u * 64 + b];
    __syncthreads();
    const int w = threadIdx.x >> 5, lane = threadIdx.x & 31;
    for (int cc = w; cc < CC; cc += 8) {
        float s = 0.f;
        for (int u = lane; u < HH; u += 32) s = fmaf(hs[u], Wfc[cc * HH + u], s);
#pragma unroll
        for (int o = 16; o; o >>= 1) s += __shfl_xor_sync(0xffffffffu, s, o);
        if (lane == 0) out[b * CC + cc] = s + bfc[cc];
    }
}

// -------------------- launch --------------------
extern "C" void kernel_launch(void* const* d_in, const int* in_sizes, int n_in,
                              void* d_out, int out_size) {
    (void)in_sizes; (void)n_in; (void)out_size;
    const float* x   = (const float*)d_in[0];
    const float* Wih = (const float*)d_in[1];
    const float* Whh = (const float*)d_in[2];
    const float* bih = (const float*)d_in[3];
    const float* bhh = (const float*)d_in[4];
    const float* Wfc = (const float*)d_in[5];
    const float* bfc = (const float*)d_in[6];
    float* out = (float*)d_out;

    gemm_xg<<<dim3(G4 / 128, (BB * TT) / 128), 256>>>(x, Wih, bih, bhh);
    transpose_xg<<<dim3(TT, G4 / 64), 256>>>();

    cudaFuncSetAttribute(lstm_rec, cudaFuncAttributeMaxDynamicSharedMemorySize, SMEM_LSTM);
    lstm_rec<<<NB, 256, SMEM_LSTM>>>(Whh);

    fc_out<<<BB, 256>>>(Wfc, bfc, out);
}